// round 2
// baseline (speedup 1.0000x reference)
#include <cuda_runtime.h>
#include <math.h>

#ifndef M_PI
#define M_PI 3.14159265358979323846
#endif

// Problem constants
#define NBT 48      // B*T_IN = 4*12
#define NC  64      // WIDTH
#define NX  128
#define NY  128
#define NB  4
#define TIN 12
#define TOUT 4
#define UD  3
#define NDEPTH 4

// ---------------- scratch (device globals; allocation-free) ----------------
__device__ float g_X [NBT*NC*NX*NY];     // activation (bt,c,x,y)   201 MB
__device__ float g_Yf[NBT*NC*NX*32];     // fwd-y result (row,k32)   50 MB
__device__ float g_Z [NBT*NC*512*2];     // fwd spectrum (bt,c,mode) 12.6 MB
__device__ float g_O [NBT*NC*512*2];     // mixed spectrum           12.6 MB
__device__ float g_Xi[NBT*NC*NX*32];     // inv-x result (bt,o,x,k32)50 MB
// DFT basis tables
__device__ float g_Wfy[128*32];          // [y][k]  k<16: cos, k>=16: -sin
__device__ float g_Wfx[128*32*2];        // [x][m] (re,im) fwd e^{-i}
__device__ float g_Wix[32*128*2];        // [m][x] (re,im) inv e^{+i}/128
__device__ float g_Cy [16*128];          // inverse-y c2r cos basis
__device__ float g_Sy [16*128];          // inverse-y c2r sin basis

// ---------------- table init (exact angle reduction, double trig) ----------
__global__ void init_tables_kernel() {
    int tid = blockIdx.x * blockDim.x + threadIdx.x;
    if (tid < 128*32) {
        // Wfy: y = tid>>5, k = tid&31
        int y = tid >> 5, k = tid & 31;
        int kk = k & 15;
        double th = (2.0 * M_PI / 128.0) * (double)((kk * y) & 127);
        g_Wfy[tid] = (k < 16) ? (float)cos(th) : (float)(-sin(th));
    }
    if (tid < 128*32) {
        // Wfx: x = tid>>5, m = tid&31 ; kx = m<16 ? m : 96+m (=112..127)
        int x = tid >> 5, m = tid & 31;
        int kx = (m < 16) ? m : (96 + m);
        double th = (2.0 * M_PI / 128.0) * (double)((kx * x) & 127);
        g_Wfx[2*tid]   = (float)cos(th);
        g_Wfx[2*tid+1] = (float)(-sin(th));
    }
    if (tid < 32*128) {
        // Wix: m = tid>>7, x = tid&127
        int m = tid >> 7, x = tid & 127;
        int kx = (m < 16) ? m : (96 + m);
        double th = (2.0 * M_PI / 128.0) * (double)((kx * x) & 127);
        g_Wix[2*tid]   = (float)(cos(th) / 128.0);
        g_Wix[2*tid+1] = (float)(sin(th) / 128.0);
    }
    if (tid < 16*128) {
        // Cy/Sy: k = tid>>7, y = tid&127  (c2r: imag of DC bin ignored)
        int k = tid >> 7, y = tid & 127;
        if (k == 0) { g_Cy[tid] = 1.0f/128.0f; g_Sy[tid] = 0.0f; }
        else {
            double th = (2.0 * M_PI / 128.0) * (double)((k * y) & 127);
            g_Cy[tid] = (float)( 2.0 * cos(th) / 128.0);
            g_Sy[tid] = (float)(-2.0 * sin(th) / 128.0);
        }
    }
}

// ---------------- lifting: 3 -> 64 channels --------------------------------
__global__ __launch_bounds__(256) void lift_kernel(
    const float* __restrict__ in, const float* __restrict__ Pw,
    const float* __restrict__ Pb)
{
    __shared__ float sPw[64*3];
    __shared__ float sPb[64];
    int tid = threadIdx.x;
    if (tid < 192) sPw[tid] = Pw[tid];
    if (tid < 64)  sPb[tid] = Pb[tid];
    __syncthreads();
    int idx = blockIdx.x * 256 + tid;            // over 48*16384
    int bt = idx >> 14, xy = idx & 16383;
    float a0 = in[(bt*3 + 0)*16384 + xy];
    float a1 = in[(bt*3 + 1)*16384 + xy];
    float a2 = in[(bt*3 + 2)*16384 + xy];
    float* dst = g_X + (size_t)bt * NC * 16384 + xy;
#pragma unroll
    for (int o = 0; o < 64; o++)
        dst[(size_t)o * 16384] = sPb[o] + sPw[o*3]*a0 + sPw[o*3+1]*a1 + sPw[o*3+2]*a2;
}

// ---------------- forward DFT over y: rows of 128 -> 32 (16 re + 16 im) ----
__global__ __launch_bounds__(256) void fwd_y_kernel() {
    __shared__ float sW[128*32];
    __shared__ float sR[32*128];
    int tid = threadIdx.x;
    for (int i = tid; i < 4096; i += 256) sW[i] = g_Wfy[i];
    size_t rowBase = (size_t)blockIdx.x * 32;
    const float* src = g_X + rowBase * 128;
    for (int i = tid; i < 4096; i += 256) sR[i] = src[i];
    __syncthreads();
    int warp = tid >> 5, lane = tid & 31;
    const float* r0 = sR + warp * 4 * 128;
    float a0 = 0.f, a1 = 0.f, a2 = 0.f, a3 = 0.f;
#pragma unroll 4
    for (int y = 0; y < 128; y++) {
        float w = sW[y*32 + lane];
        a0 += r0[y]       * w;
        a1 += r0[128 + y] * w;
        a2 += r0[256 + y] * w;
        a3 += r0[384 + y] * w;
    }
    float* dst = g_Yf + (rowBase + warp*4) * 32 + lane;
    dst[0] = a0; dst[32] = a1; dst[64] = a2; dst[96] = a3;
}

// ---------------- forward DFT over x: (x,ky) -> (m,ky), complex ------------
__global__ __launch_bounds__(256) void fwd_x_kernel() {
    __shared__ float sY[4096];                  // one field (128 x, 32 packed)
    int tid = threadIdx.x;
    const float* src = g_Yf + (size_t)blockIdx.x * 4096;
    for (int i = tid; i < 4096; i += 256) sY[i] = src[i];
    __syncthreads();
    int m = tid >> 3;                           // 0..31
    int ky0 = (tid & 7) * 2;                    // 0,2,...,14
    float r0 = 0.f, i0 = 0.f, r1 = 0.f, i1 = 0.f;
    for (int x = 0; x < 128; x++) {
        float wr = __ldg(&g_Wfx[(x*32 + m)*2]);
        float wi = __ldg(&g_Wfx[(x*32 + m)*2 + 1]);
        float yr0 = sY[x*32 + ky0],      yi0 = sY[x*32 + 16 + ky0];
        float yr1 = sY[x*32 + ky0 + 1],  yi1 = sY[x*32 + 17 + ky0];
        r0 += yr0*wr - yi0*wi;  i0 += yr0*wi + yi0*wr;
        r1 += yr1*wr - yi1*wi;  i1 += yr1*wi + yi1*wr;
    }
    float* dst = g_Z + ((size_t)blockIdx.x * 512 + m * 16) * 2;
    dst[2*ky0]     = r0; dst[2*ky0 + 1] = i0;
    dst[2*ky0 + 2] = r1; dst[2*ky0 + 3] = i1;
}

// ---------------- per-mode 64x64 complex channel mix -----------------------
// grid (4 modeTiles x128, 12 btTiles x4, 16 oTiles x4), 128 threads (1/mode)
__global__ __launch_bounds__(128) void mode_mix_kernel(
    const float* __restrict__ w1r, const float* __restrict__ w1i,
    const float* __restrict__ w2r, const float* __restrict__ w2i)
{
    int mode = blockIdx.x * 128 + threadIdx.x;        // 0..511
    int half = mode >> 8;                             // 0 -> w1, 1 -> w2
    int ml   = mode & 255;
    const float* Wr = half ? w2r : w1r;
    const float* Wi = half ? w2i : w1i;
    int bt0 = blockIdx.y * 4, o0 = blockIdx.z * 4;
    float accR[4][4] = {}, accI[4][4] = {};
    for (int i = 0; i < 64; i++) {
        float zr[4], zi[4];
#pragma unroll
        for (int b = 0; b < 4; b++) {
            float2 z = *(const float2*)(g_Z + (((size_t)(bt0+b)*64 + i)*512 + mode)*2);
            zr[b] = z.x; zi[b] = z.y;
        }
#pragma unroll
        for (int o = 0; o < 4; o++) {
            float wr = __ldg(Wr + ((size_t)i*64 + (o0+o))*256 + ml);
            float wi = __ldg(Wi + ((size_t)i*64 + (o0+o))*256 + ml);
#pragma unroll
            for (int b = 0; b < 4; b++) {
                accR[b][o] += zr[b]*wr - zi[b]*wi;
                accI[b][o] += zr[b]*wi + zi[b]*wr;
            }
        }
    }
#pragma unroll
    for (int b = 0; b < 4; b++)
#pragma unroll
        for (int o = 0; o < 4; o++) {
            float2* dst = (float2*)(g_O + (((size_t)(bt0+b)*64 + (o0+o))*512 + mode)*2);
            *dst = make_float2(accR[b][o], accI[b][o]);
        }
}

// ---------------- inverse DFT over x: (m,ky) -> (x,ky), complex ------------
__global__ __launch_bounds__(256) void inv_x_kernel() {
    __shared__ float sO[1024];                   // one field, 512 complex
    int tid = threadIdx.x;
    const float* src = g_O + (size_t)blockIdx.x * 1024;
    for (int i = tid; i < 1024; i += 256) sO[i] = src[i];
    __syncthreads();
    int x = tid >> 1;
    int kb = (tid & 1) * 8;
    float ar[8] = {}, ai[8] = {};
    for (int m = 0; m < 32; m++) {
        float wr = __ldg(&g_Wix[(m*128 + x)*2]);
        float wi = __ldg(&g_Wix[(m*128 + x)*2 + 1]);
#pragma unroll
        for (int k = 0; k < 8; k++) {
            float pr = sO[(m*16 + kb + k)*2];
            float pi = sO[(m*16 + kb + k)*2 + 1];
            ar[k] += pr*wr - pi*wi;
            ai[k] += pr*wi + pi*wr;
        }
    }
    float* dst = g_Xi + ((size_t)blockIdx.x * 128 + x) * 32;
#pragma unroll
    for (int k = 0; k < 8; k++) { dst[kb + k] = ar[k]; dst[16 + kb + k] = ai[k]; }
}

// ---------------- fused: inv-y + 1x1 mix + LN + GELU + context, in place ---
// one block per (bt, x) line; 256 threads; dynamic smem 108288 B
__global__ __launch_bounds__(256) void fused_tail_kernel(
    const float* __restrict__ gctxd,   // ctx for this depth: (bt,c,64,64)
    const float* __restrict__ llw,     // (64 o, 64 c)
    const float* __restrict__ llb,     // (64)
    const float* __restrict__ lng, const float* __restrict__ lnb)
{
    extern __shared__ float sm[];
    float* sX   = sm;            // 8192   (c,y)
    float* sV   = sm + 8192;     // 8192   (o,y)
    float* sXi  = sm + 16384;    // 2048   (o,32)
    float* sLL  = sm + 18432;    // 4096   (o,c)
    float* sCy  = sm + 22528;    // 2048
    float* sSy  = sm + 24576;    // 2048
    float* sMu  = sm + 26624;    // 128
    float* sRs  = sm + 26752;    // 128
    float* sLNg = sm + 26880;    // 64
    float* sLNb = sm + 26944;    // 64
    float* sLLb = sm + 27008;    // 64

    int tid = threadIdx.x;
    int x   = blockIdx.x;
    int bt  = blockIdx.y;

    // phase 1: loads
    for (int i = tid; i < 8192; i += 256) {
        int c = i >> 7, y = i & 127;
        sX[i] = g_X[(((size_t)bt*64 + c)*128 + x)*128 + y];
    }
    for (int i = tid; i < 2048; i += 256) {
        int o = i >> 5, k = i & 31;
        sXi[i] = g_Xi[(((size_t)bt*64 + o)*128 + x)*32 + k];
    }
    for (int i = tid; i < 4096; i += 256) sLL[i] = llw[i];
    for (int i = tid; i < 2048; i += 256) { sCy[i] = g_Cy[i]; sSy[i] = g_Sy[i]; }
    if (tid < 64) { sLNg[tid] = lng[tid]; sLNb[tid] = lnb[tid]; sLLb[tid] = llb[tid]; }
    __syncthreads();

    // phase 2: V[o][y] = local-linear + inverse-y
    int o0  = (tid >> 5) * 8;           // 8 o per thread
    int tx4 = (tid & 31) * 4;           // 4 y per thread
    float acc[8][4] = {};
    for (int c = 0; c < 64; c++) {
        float4 xv = *(const float4*)(sX + c*128 + tx4);
#pragma unroll
        for (int oo = 0; oo < 8; oo++) {
            float w = sLL[(o0 + oo)*64 + c];
            acc[oo][0] += w * xv.x; acc[oo][1] += w * xv.y;
            acc[oo][2] += w * xv.z; acc[oo][3] += w * xv.w;
        }
    }
#pragma unroll
    for (int ky = 0; ky < 16; ky++) {
        float4 cy = *(const float4*)(sCy + ky*128 + tx4);
        float4 sy = *(const float4*)(sSy + ky*128 + tx4);
#pragma unroll
        for (int oo = 0; oo < 8; oo++) {
            float xr = sXi[(o0 + oo)*32 + ky];
            float xi = sXi[(o0 + oo)*32 + 16 + ky];
            acc[oo][0] += xr*cy.x + xi*sy.x;
            acc[oo][1] += xr*cy.y + xi*sy.y;
            acc[oo][2] += xr*cy.z + xi*sy.z;
            acc[oo][3] += xr*cy.w + xi*sy.w;
        }
    }
#pragma unroll
    for (int oo = 0; oo < 8; oo++) {
        float b = sLLb[o0 + oo];
        *(float4*)(sV + (o0 + oo)*128 + tx4) =
            make_float4(acc[oo][0]+b, acc[oo][1]+b, acc[oo][2]+b, acc[oo][3]+b);
    }
    __syncthreads();

    // phase 3: layernorm stats per y
    if (tid < 128) {
        float s = 0.f, ss = 0.f;
        for (int o = 0; o < 64; o++) {
            float v = sV[o*128 + tid];
            s += v; ss += v*v;
        }
        float mu = s * (1.0f/64.0f);
        float var = ss * (1.0f/64.0f) - mu*mu;
        sMu[tid] = mu;
        sRs[tid] = rsqrtf(var + 1e-5f);
    }
    __syncthreads();

    // phase 4: normalize + gelu + bilinear context + write back (in place)
    // x-direction interpolation (shared by whole block)
    float cxf = x * 0.5f - 0.25f;
    int ix0 = (int)floorf(cxf);
    float wx1 = cxf - (float)ix0, wx0 = 1.0f - wx1;
    int cx0 = min(63, max(0, ix0));
    int cx1 = min(63, max(0, ix0 + 1));
    // y-direction (constant per thread across j)
    int y = tid & 127;
    float cyf = y * 0.5f - 0.25f;
    int iy0 = (int)floorf(cyf);
    float wy1 = cyf - (float)iy0, wy0 = 1.0f - wy1;
    int cy0 = min(63, max(0, iy0));
    int cy1 = min(63, max(0, iy0 + 1));

    for (int j = 0; j < 32; j++) {
        int idx = j * 256 + tid;
        int o = idx >> 7;                  // y == tid & 127 (constant)
        float v = sV[o*128 + y];
        v = (v - sMu[y]) * sRs[y] * sLNg[o] + sLNb[o];
        v = 0.5f * v * (1.0f + erff(v * 0.70710678118654752440f));
        const float* gc = gctxd + ((size_t)bt*64 + o) * 4096;
        float g = wx0 * (wy0 * __ldg(gc + cx0*64 + cy0) + wy1 * __ldg(gc + cx0*64 + cy1))
                + wx1 * (wy0 * __ldg(gc + cx1*64 + cy0) + wy1 * __ldg(gc + cx1*64 + cy1));
        g_X[(((size_t)bt*64 + o)*128 + x)*128 + y] = v + g;
    }
}

// ---------------- temporal aggregation + projection ------------------------
__global__ __launch_bounds__(256) void head_kernel(
    const float* __restrict__ Wtw, const float* __restrict__ Wtb,
    const float* __restrict__ Qw,  const float* __restrict__ Qb,
    float* __restrict__ out)
{
    __shared__ float sWt[48], sWtb[4], sQ[192], sQb[3], sQS[3];
    int tid = threadIdx.x;
    if (tid < 48)  sWt[tid]  = Wtw[tid];
    if (tid < 4)   sWtb[tid] = Wtb[tid];
    if (tid < 192) sQ[tid]   = Qw[tid];
    if (tid < 3)   sQb[tid]  = Qb[tid];
    __syncthreads();
    if (tid < 3) {
        float s = 0.f;
        for (int c = 0; c < 64; c++) s += sQ[tid*64 + c];
        sQS[tid] = s;
    }
    __syncthreads();
    int idx = blockIdx.x * 256 + tid;           // over 4*16384
    int b = idx >> 14, xy = idx & 16383;
    float acc[TOUT][UD] = {};
    for (int c = 0; c < 64; c++) {
        float xv[TIN];
#pragma unroll
        for (int t = 0; t < TIN; t++)
            xv[t] = g_X[(((size_t)(b*TIN + t))*64 + c)*16384 + xy];
        float tt[TOUT];
#pragma unroll
        for (int o = 0; o < TOUT; o++) {
            float s = 0.f;
#pragma unroll
            for (int t = 0; t < TIN; t++) s += sWt[o*TIN + t] * xv[t];
            tt[o] = s;
        }
#pragma unroll
        for (int u = 0; u < UD; u++) {
            float q = sQ[u*64 + c];
#pragma unroll
            for (int o = 0; o < TOUT; o++) acc[o][u] += q * tt[o];
        }
    }
#pragma unroll
    for (int o = 0; o < TOUT; o++)
#pragma unroll
        for (int u = 0; u < UD; u++)
            out[(((size_t)b*TOUT + o)*UD + u)*16384 + xy] =
                acc[o][u] + sWtb[o]*sQS[u] + sQb[u];
}

// ---------------- launcher --------------------------------------------------
extern "C" void kernel_launch(void* const* d_in, const int* in_sizes, int n_in,
                              void* d_out, int out_size)
{
    const float* input = (const float*)d_in[0];
    const float* gctx  = (const float*)d_in[1];
    const float* P_w   = (const float*)d_in[2];
    const float* P_b   = (const float*)d_in[3];
    const float* Q_w   = (const float*)d_in[4];
    const float* Q_b   = (const float*)d_in[5];
    const float* Wt_w  = (const float*)d_in[6];
    const float* Wt_b  = (const float*)d_in[7];
    const float* w1r   = (const float*)d_in[8];
    const float* w1i   = (const float*)d_in[9];
    const float* w2r   = (const float*)d_in[10];
    const float* w2i   = (const float*)d_in[11];
    const float* ll_w  = (const float*)d_in[12];
    const float* ll_b  = (const float*)d_in[13];
    const float* ln_g  = (const float*)d_in[14];
    const float* ln_b  = (const float*)d_in[15];
    float* out = (float*)d_out;

    const int FUSED_SMEM = 27072 * 4;  // 108288 bytes
    cudaFuncSetAttribute(fused_tail_kernel,
                         cudaFuncAttributeMaxDynamicSharedMemorySize, FUSED_SMEM);

    init_tables_kernel<<<16, 256>>>();
    lift_kernel<<<3072, 256>>>(input, P_w, P_b);

    const size_t SPEC_D = (size_t)64*64*16*16;   // per-depth spectral weight block
    for (int d = 0; d < NDEPTH; d++) {
        fwd_y_kernel<<<12288, 256>>>();
        fwd_x_kernel<<<NBT*NC, 256>>>();
        dim3 g3(4, 12, 16);
        mode_mix_kernel<<<g3, 128>>>(w1r + d*SPEC_D, w1i + d*SPEC_D,
                                     w2r + d*SPEC_D, w2i + d*SPEC_D);
        inv_x_kernel<<<NBT*NC, 256>>>();
        dim3 g5(128, NBT);
        fused_tail_kernel<<<g5, 256, FUSED_SMEM>>>(
            gctx + (size_t)d*NBT*64*4096,
            ll_w + (size_t)d*4096, ll_b + d*64, ln_g + d*64, ln_b + d*64);
    }
    head_kernel<<<256, 256>>>(Wt_w, Wt_b, Q_w, Q_b, out);
}

// round 3
// speedup vs baseline: 1.1253x; 1.1253x over previous
#include <cuda_runtime.h>
#include <math.h>

#ifndef M_PI
#define M_PI 3.14159265358979323846
#endif

// Problem constants
#define NBT 48      // B*T_IN = 4*12
#define NC  64      // WIDTH
#define NX  128
#define NY  128
#define NB  4
#define TIN 12
#define TOUT 4
#define UD  3
#define NDEPTH 4

typedef unsigned long long u64;

// ---------------- packed f32x2 helpers (sm_100+) ---------------------------
__device__ __forceinline__ u64 f2fma(u64 a, u64 b, u64 c) {
    u64 r; asm("fma.rn.f32x2 %0,%1,%2,%3;" : "=l"(r) : "l"(a), "l"(b), "l"(c)); return r;
}
__device__ __forceinline__ u64 f2sub(u64 a, u64 b) {
    u64 r; asm("sub.rn.f32x2 %0,%1,%2;" : "=l"(r) : "l"(a), "l"(b)); return r;
}
__device__ __forceinline__ u64 f2pack(float lo, float hi) {
    u64 r; asm("mov.b64 %0,{%1,%2};" : "=l"(r) : "f"(lo), "f"(hi)); return r;
}
__device__ __forceinline__ u64 f2dup(float v) { return f2pack(v, v); }
__device__ __forceinline__ float2 f2unpack(u64 a) {
    float2 r; asm("mov.b64 {%0,%1},%2;" : "=f"(r.x), "=f"(r.y) : "l"(a)); return r;
}
__device__ __forceinline__ u64 f2neg(u64 a) { return a ^ 0x8000000080000000ULL; }

// ---------------- scratch (device globals; allocation-free) ----------------
__device__ float g_X [NBT*NC*NX*NY];     // activation (bt,c,x,y)
__device__ float g_Yf[NBT*NC*NX*32];     // fwd-y result (row, 16re+16im)
__device__ float g_Zr[NBT*NC*512];       // fwd spectrum real (bt,c,mode)
__device__ float g_Zi[NBT*NC*512];       // fwd spectrum imag
__device__ float g_Or[NBT*NC*512];       // mixed spectrum real
__device__ float g_Oi[NBT*NC*512];       // mixed spectrum imag
__device__ float g_Xi[NBT*NC*NX*32];     // inv-x result (bt,o,x,16re+16im)
// DFT basis tables
__device__ float g_Wfy2[64*32*2];        // [ypair][k] packed pair {w(2y,k), w(2y+1,k)}
__device__ float g_Wfx[128*32*2];        // [x][m] (re,im) fwd e^{-i}
__device__ float g_Wix[32*128*2];        // [m][x] (re,im) inv e^{+i}/128
__device__ float g_Cy [16*128];          // inverse-y c2r cos basis
__device__ float g_Sy [16*128];          // inverse-y c2r sin basis

// ---------------- table init (exact angle reduction, double trig) ----------
__global__ void init_tables_kernel() {
    int tid = blockIdx.x * blockDim.x + threadIdx.x;
    if (tid < 64*32) {
        // Wfy2: yp = tid>>5, k = tid&31 ; pair over y = 2yp, 2yp+1
        int yp = tid >> 5, k = tid & 31;
        int kk = k & 15;
        for (int j = 0; j < 2; j++) {
            int y = 2*yp + j;
            double th = (2.0 * M_PI / 128.0) * (double)((kk * y) & 127);
            g_Wfy2[tid*2 + j] = (k < 16) ? (float)cos(th) : (float)(-sin(th));
        }
    }
    if (tid < 128*32) {
        // Wfx: x = tid>>5, m = tid&31 ; kx = m<16 ? m : 96+m (=112..127)
        int x = tid >> 5, m = tid & 31;
        int kx = (m < 16) ? m : (96 + m);
        double th = (2.0 * M_PI / 128.0) * (double)((kx * x) & 127);
        g_Wfx[2*tid]   = (float)cos(th);
        g_Wfx[2*tid+1] = (float)(-sin(th));
    }
    if (tid < 32*128) {
        // Wix: m = tid>>7, x = tid&127
        int m = tid >> 7, x = tid & 127;
        int kx = (m < 16) ? m : (96 + m);
        double th = (2.0 * M_PI / 128.0) * (double)((kx * x) & 127);
        g_Wix[2*tid]   = (float)(cos(th) / 128.0);
        g_Wix[2*tid+1] = (float)(sin(th) / 128.0);
    }
    if (tid < 16*128) {
        // Cy/Sy: k = tid>>7, y = tid&127  (c2r: imag of DC bin ignored)
        int k = tid >> 7, y = tid & 127;
        if (k == 0) { g_Cy[tid] = 1.0f/128.0f; g_Sy[tid] = 0.0f; }
        else {
            double th = (2.0 * M_PI / 128.0) * (double)((k * y) & 127);
            g_Cy[tid] = (float)( 2.0 * cos(th) / 128.0);
            g_Sy[tid] = (float)(-2.0 * sin(th) / 128.0);
        }
    }
}

// ---------------- lifting: 3 -> 64 channels --------------------------------
__global__ __launch_bounds__(256) void lift_kernel(
    const float* __restrict__ in, const float* __restrict__ Pw,
    const float* __restrict__ Pb)
{
    __shared__ float sPw[64*3];
    __shared__ float sPb[64];
    int tid = threadIdx.x;
    if (tid < 192) sPw[tid] = Pw[tid];
    if (tid < 64)  sPb[tid] = Pb[tid];
    __syncthreads();
    int idx = blockIdx.x * 256 + tid;            // over 48*16384
    int bt = idx >> 14, xy = idx & 16383;
    float a0 = in[(bt*3 + 0)*16384 + xy];
    float a1 = in[(bt*3 + 1)*16384 + xy];
    float a2 = in[(bt*3 + 2)*16384 + xy];
    float* dst = g_X + (size_t)bt * NC * 16384 + xy;
#pragma unroll
    for (int o = 0; o < 64; o++)
        dst[(size_t)o * 16384] = sPb[o] + sPw[o*3]*a0 + sPw[o*3+1]*a1 + sPw[o*3+2]*a2;
}

// ---------------- forward DFT over y (packed y-pairs) ----------------------
// block = 32 rows; warp computes 4 rows x 32 k
__global__ __launch_bounds__(256) void fwd_y_kernel() {
    __shared__ float sW2[64*32*2];    // 16KB packed pair table
    __shared__ float sR[32*128];      // 16KB rows
    int tid = threadIdx.x;
    for (int i = tid; i < 4096; i += 256) sW2[i] = g_Wfy2[i];
    size_t rowBase = (size_t)blockIdx.x * 32;
    const float* src = g_X + rowBase * 128;
    for (int i = tid; i < 4096; i += 256) sR[i] = src[i];
    __syncthreads();
    int warp = tid >> 5, lane = tid & 31;
    const float* r0 = sR + warp * 4 * 128;
    const u64* w2 = (const u64*)sW2;
    u64 a0 = 0ULL, a1 = 0ULL, a2 = 0ULL, a3 = 0ULL;
#pragma unroll 8
    for (int yp = 0; yp < 64; yp++) {
        u64 w  = w2[yp*32 + lane];
        u64 rA = *(const u64*)(r0 + 2*yp);
        u64 rB = *(const u64*)(r0 + 128 + 2*yp);
        u64 rC = *(const u64*)(r0 + 256 + 2*yp);
        u64 rD = *(const u64*)(r0 + 384 + 2*yp);
        a0 = f2fma(rA, w, a0);
        a1 = f2fma(rB, w, a1);
        a2 = f2fma(rC, w, a2);
        a3 = f2fma(rD, w, a3);
    }
    float2 p0 = f2unpack(a0), p1 = f2unpack(a1), p2 = f2unpack(a2), p3 = f2unpack(a3);
    float* dst = g_Yf + (rowBase + warp*4) * 32 + lane;
    dst[0]  = p0.x + p0.y;
    dst[32] = p1.x + p1.y;
    dst[64] = p2.x + p2.y;
    dst[96] = p3.x + p3.y;
}

// ---------------- forward DFT over x -> planar spectrum --------------------
__global__ __launch_bounds__(256) void fwd_x_kernel() {
    __shared__ float sY[4096];
    int tid = threadIdx.x;
    const float* src = g_Yf + (size_t)blockIdx.x * 4096;
    for (int i = tid; i < 4096; i += 256) sY[i] = src[i];
    __syncthreads();
    int m   = tid >> 3;                 // 0..31
    int ky0 = (tid & 7) * 2;            // 0,2,...,14
    u64 rA = 0ULL, rB = 0ULL, ii = 0ULL;   // rr = rA - rB
#pragma unroll 4
    for (int x = 0; x < 128; x++) {
        float2 w = *(const float2*)(g_Wfx + (x*32 + m)*2);
        u64 wr2 = f2dup(w.x), wi2 = f2dup(w.y);
        u64 yr2 = *(const u64*)(sY + x*32 + ky0);
        u64 yi2 = *(const u64*)(sY + x*32 + 16 + ky0);
        rA = f2fma(yr2, wr2, rA);
        rB = f2fma(yi2, wi2, rB);
        ii = f2fma(yr2, wi2, ii);
        ii = f2fma(yi2, wr2, ii);
    }
    size_t base = (size_t)blockIdx.x * 512 + m*16 + ky0;
    *(u64*)(g_Zr + base) = f2sub(rA, rB);
    *(u64*)(g_Zi + base) = ii;
}

// ---------------- per-mode 64x64 complex channel mix (2 modes/thread) ------
// grid (2 modePairTiles x128, 12 btTiles x4, 16 oTiles x4), 128 threads
__global__ __launch_bounds__(128) void mode_mix_kernel(
    const float* __restrict__ w1r, const float* __restrict__ w1i,
    const float* __restrict__ w2r, const float* __restrict__ w2i)
{
    int mp    = blockIdx.x * 128 + threadIdx.x;   // mode-pair 0..255
    int mode0 = mp * 2;
    int half  = mode0 >> 8;
    int ml    = mode0 & 255;
    const float* Wr = half ? w2r : w1r;
    const float* Wi = half ? w2i : w1i;
    int bt0 = blockIdx.y * 4, o0 = blockIdx.z * 4;
    u64 aR[4][4], aI[4][4];
#pragma unroll
    for (int b = 0; b < 4; b++)
#pragma unroll
        for (int o = 0; o < 4; o++) { aR[b][o] = 0ULL; aI[b][o] = 0ULL; }

    for (int i = 0; i < 64; i++) {
        u64 zr[4], zi[4];
#pragma unroll
        for (int b = 0; b < 4; b++) {
            size_t zb = ((size_t)(bt0 + b)*64 + i)*512 + mode0;
            zr[b] = *(const u64*)(g_Zr + zb);
            zi[b] = *(const u64*)(g_Zi + zb);
        }
#pragma unroll
        for (int o = 0; o < 4; o++) {
            size_t wb = ((size_t)i*64 + (o0 + o))*256 + ml;
            u64 wr2  = *(const u64*)(Wr + wb);
            u64 wi2  = *(const u64*)(Wi + wb);
            u64 wi2n = f2neg(wi2);
#pragma unroll
            for (int b = 0; b < 4; b++) {
                aR[b][o] = f2fma(zr[b], wr2,  aR[b][o]);
                aR[b][o] = f2fma(zi[b], wi2n, aR[b][o]);
                aI[b][o] = f2fma(zr[b], wi2,  aI[b][o]);
                aI[b][o] = f2fma(zi[b], wr2,  aI[b][o]);
            }
        }
    }
#pragma unroll
    for (int b = 0; b < 4; b++)
#pragma unroll
        for (int o = 0; o < 4; o++) {
            size_t ob = ((size_t)(bt0 + b)*64 + (o0 + o))*512 + mode0;
            *(u64*)(g_Or + ob) = aR[b][o];
            *(u64*)(g_Oi + ob) = aI[b][o];
        }
}

// ---------------- inverse DFT over x ---------------------------------------
__global__ __launch_bounds__(256) void inv_x_kernel() {
    __shared__ float sOr[512], sOi[512];
    int tid = threadIdx.x;
    const float* srcr = g_Or + (size_t)blockIdx.x * 512;
    const float* srci = g_Oi + (size_t)blockIdx.x * 512;
    for (int i = tid; i < 512; i += 256) { sOr[i] = srcr[i]; sOi[i] = srci[i]; }
    __syncthreads();
    int x  = tid >> 1;
    int kb = (tid & 1) * 8;             // this thread: ky kb..kb+7 (4 pairs)
    u64 arA[4], arB[4], ai[4];
#pragma unroll
    for (int j = 0; j < 4; j++) { arA[j] = 0ULL; arB[j] = 0ULL; ai[j] = 0ULL; }
#pragma unroll 4
    for (int m = 0; m < 32; m++) {
        float2 w = *(const float2*)(g_Wix + (m*128 + x)*2);
        u64 wr2 = f2dup(w.x), wi2 = f2dup(w.y);
#pragma unroll
        for (int j = 0; j < 4; j++) {
            u64 pr = *(const u64*)(sOr + m*16 + kb + 2*j);
            u64 pi = *(const u64*)(sOi + m*16 + kb + 2*j);
            arA[j] = f2fma(pr, wr2, arA[j]);
            arB[j] = f2fma(pi, wi2, arB[j]);
            ai[j]  = f2fma(pr, wi2, ai[j]);
            ai[j]  = f2fma(pi, wr2, ai[j]);
        }
    }
    float* dst = g_Xi + ((size_t)blockIdx.x * 128 + x) * 32;
#pragma unroll
    for (int j = 0; j < 4; j++) {
        *(u64*)(dst + kb + 2*j)      = f2sub(arA[j], arB[j]);
        *(u64*)(dst + 16 + kb + 2*j) = ai[j];
    }
}

// ---------------- fused: inv-y + 1x1 mix + LN + GELU + context, in place ---
// one block per (bt, x) line; 256 threads; dynamic smem 108288 B
__global__ __launch_bounds__(256) void fused_tail_kernel(
    const float* __restrict__ gctxd,   // ctx for this depth: (bt,c,64,64)
    const float* __restrict__ llw,     // (64 o, 64 c)
    const float* __restrict__ llb,     // (64)
    const float* __restrict__ lng, const float* __restrict__ lnb)
{
    extern __shared__ float sm[];
    float* sX   = sm;            // 8192   (c,y)
    float* sV   = sm + 8192;     // 8192   (o,y)
    float* sXi  = sm + 16384;    // 2048   (o,32)
    float* sLL  = sm + 18432;    // 4096   (o,c)
    float* sCy  = sm + 22528;    // 2048
    float* sSy  = sm + 24576;    // 2048
    float* sMu  = sm + 26624;    // 128
    float* sRs  = sm + 26752;    // 128
    float* sLNg = sm + 26880;    // 64
    float* sLNb = sm + 26944;    // 64
    float* sLLb = sm + 27008;    // 64

    int tid = threadIdx.x;
    int x   = blockIdx.x;
    int bt  = blockIdx.y;

    // phase 1: loads
    for (int i = tid; i < 8192; i += 256) {
        int c = i >> 7, y = i & 127;
        sX[i] = g_X[(((size_t)bt*64 + c)*128 + x)*128 + y];
    }
    for (int i = tid; i < 2048; i += 256) {
        int o = i >> 5, k = i & 31;
        sXi[i] = g_Xi[(((size_t)bt*64 + o)*128 + x)*32 + k];
    }
    for (int i = tid; i < 4096; i += 256) sLL[i] = llw[i];
    for (int i = tid; i < 2048; i += 256) { sCy[i] = g_Cy[i]; sSy[i] = g_Sy[i]; }
    if (tid < 64) { sLNg[tid] = lng[tid]; sLNb[tid] = lnb[tid]; sLLb[tid] = llb[tid]; }
    __syncthreads();

    // phase 2: V[o][y] = local-linear + inverse-y (packed f32x2)
    int o0  = (tid >> 5) * 8;           // 8 o per thread
    int tx4 = (tid & 31) * 4;           // 4 y per thread = 2 pairs
    u64 acc0[8], acc1[8];
#pragma unroll
    for (int oo = 0; oo < 8; oo++) { acc0[oo] = 0ULL; acc1[oo] = 0ULL; }

    for (int c = 0; c < 64; c++) {
        ulonglong2 xv = *(const ulonglong2*)(sX + c*128 + tx4);
#pragma unroll
        for (int oo = 0; oo < 8; oo++) {
            u64 w2 = f2dup(sLL[(o0 + oo)*64 + c]);
            acc0[oo] = f2fma(xv.x, w2, acc0[oo]);
            acc1[oo] = f2fma(xv.y, w2, acc1[oo]);
        }
    }
#pragma unroll
    for (int ky = 0; ky < 16; ky++) {
        ulonglong2 cy = *(const ulonglong2*)(sCy + ky*128 + tx4);
        ulonglong2 sy = *(const ulonglong2*)(sSy + ky*128 + tx4);
#pragma unroll
        for (int oo = 0; oo < 8; oo++) {
            u64 xr2 = f2dup(sXi[(o0 + oo)*32 + ky]);
            u64 xi2 = f2dup(sXi[(o0 + oo)*32 + 16 + ky]);
            acc0[oo] = f2fma(xr2, cy.x, acc0[oo]);
            acc0[oo] = f2fma(xi2, sy.x, acc0[oo]);
            acc1[oo] = f2fma(xr2, cy.y, acc1[oo]);
            acc1[oo] = f2fma(xi2, sy.y, acc1[oo]);
        }
    }
#pragma unroll
    for (int oo = 0; oo < 8; oo++) {
        float b = sLLb[o0 + oo];
        float2 v0 = f2unpack(acc0[oo]);
        float2 v1 = f2unpack(acc1[oo]);
        *(float4*)(sV + (o0 + oo)*128 + tx4) =
            make_float4(v0.x + b, v0.y + b, v1.x + b, v1.y + b);
    }
    __syncthreads();

    // phase 3: layernorm stats per y
    if (tid < 128) {
        float s = 0.f, ss = 0.f;
        for (int o = 0; o < 64; o++) {
            float v = sV[o*128 + tid];
            s += v; ss += v*v;
        }
        float mu = s * (1.0f/64.0f);
        float var = ss * (1.0f/64.0f) - mu*mu;
        sMu[tid] = mu;
        sRs[tid] = rsqrtf(var + 1e-5f);
    }
    __syncthreads();

    // phase 4: normalize + gelu + bilinear context + write back (in place)
    float cxf = x * 0.5f - 0.25f;
    int ix0 = (int)floorf(cxf);
    float wx1 = cxf - (float)ix0, wx0 = 1.0f - wx1;
    int cx0 = min(63, max(0, ix0));
    int cx1 = min(63, max(0, ix0 + 1));
    int y = tid & 127;
    float cyf = y * 0.5f - 0.25f;
    int iy0 = (int)floorf(cyf);
    float wy1 = cyf - (float)iy0, wy0 = 1.0f - wy1;
    int cy0 = min(63, max(0, iy0));
    int cy1 = min(63, max(0, iy0 + 1));

    for (int j = 0; j < 32; j++) {
        int idx = j * 256 + tid;
        int o = idx >> 7;
        float v = sV[o*128 + y];
        v = (v - sMu[y]) * sRs[y] * sLNg[o] + sLNb[o];
        v = 0.5f * v * (1.0f + erff(v * 0.70710678118654752440f));
        const float* gc = gctxd + ((size_t)bt*64 + o) * 4096;
        float g = wx0 * (wy0 * __ldg(gc + cx0*64 + cy0) + wy1 * __ldg(gc + cx0*64 + cy1))
                + wx1 * (wy0 * __ldg(gc + cx1*64 + cy0) + wy1 * __ldg(gc + cx1*64 + cy1));
        g_X[(((size_t)bt*64 + o)*128 + x)*128 + y] = v + g;
    }
}

// ---------------- temporal aggregation + projection ------------------------
__global__ __launch_bounds__(256) void head_kernel(
    const float* __restrict__ Wtw, const float* __restrict__ Wtb,
    const float* __restrict__ Qw,  const float* __restrict__ Qb,
    float* __restrict__ out)
{
    __shared__ float sWt[48], sWtb[4], sQ[192], sQb[3], sQS[3];
    int tid = threadIdx.x;
    if (tid < 48)  sWt[tid]  = Wtw[tid];
    if (tid < 4)   sWtb[tid] = Wtb[tid];
    if (tid < 192) sQ[tid]   = Qw[tid];
    if (tid < 3)   sQb[tid]  = Qb[tid];
    __syncthreads();
    if (tid < 3) {
        float s = 0.f;
        for (int c = 0; c < 64; c++) s += sQ[tid*64 + c];
        sQS[tid] = s;
    }
    __syncthreads();
    int idx = blockIdx.x * 256 + tid;           // over 4*16384
    int b = idx >> 14, xy = idx & 16383;
    float acc[TOUT][UD] = {};
    for (int c = 0; c < 64; c++) {
        float xv[TIN];
#pragma unroll
        for (int t = 0; t < TIN; t++)
            xv[t] = g_X[(((size_t)(b*TIN + t))*64 + c)*16384 + xy];
        float tt[TOUT];
#pragma unroll
        for (int o = 0; o < TOUT; o++) {
            float s = 0.f;
#pragma unroll
            for (int t = 0; t < TIN; t++) s += sWt[o*TIN + t] * xv[t];
            tt[o] = s;
        }
#pragma unroll
        for (int u = 0; u < UD; u++) {
            float q = sQ[u*64 + c];
#pragma unroll
            for (int o = 0; o < TOUT; o++) acc[o][u] += q * tt[o];
        }
    }
#pragma unroll
    for (int o = 0; o < TOUT; o++)
#pragma unroll
        for (int u = 0; u < UD; u++)
            out[(((size_t)b*TOUT + o)*UD + u)*16384 + xy] =
                acc[o][u] + sWtb[o]*sQS[u] + sQb[u];
}

// ---------------- launcher --------------------------------------------------
extern "C" void kernel_launch(void* const* d_in, const int* in_sizes, int n_in,
                              void* d_out, int out_size)
{
    const float* input = (const float*)d_in[0];
    const float* gctx  = (const float*)d_in[1];
    const float* P_w   = (const float*)d_in[2];
    const float* P_b   = (const float*)d_in[3];
    const float* Q_w   = (const float*)d_in[4];
    const float* Q_b   = (const float*)d_in[5];
    const float* Wt_w  = (const float*)d_in[6];
    const float* Wt_b  = (const float*)d_in[7];
    const float* w1r   = (const float*)d_in[8];
    const float* w1i   = (const float*)d_in[9];
    const float* w2r   = (const float*)d_in[10];
    const float* w2i   = (const float*)d_in[11];
    const float* ll_w  = (const float*)d_in[12];
    const float* ll_b  = (const float*)d_in[13];
    const float* ln_g  = (const float*)d_in[14];
    const float* ln_b  = (const float*)d_in[15];
    float* out = (float*)d_out;

    const int FUSED_SMEM = 27072 * 4;  // 108288 bytes
    cudaFuncSetAttribute(fused_tail_kernel,
                         cudaFuncAttributeMaxDynamicSharedMemorySize, FUSED_SMEM);

    init_tables_kernel<<<16, 256>>>();
    lift_kernel<<<3072, 256>>>(input, P_w, P_b);

    const size_t SPEC_D = (size_t)64*64*16*16;   // per-depth spectral weight block
    for (int d = 0; d < NDEPTH; d++) {
        fwd_y_kernel<<<12288, 256>>>();
        fwd_x_kernel<<<NBT*NC, 256>>>();
        dim3 g3(2, 12, 16);
        mode_mix_kernel<<<g3, 128>>>(w1r + d*SPEC_D, w1i + d*SPEC_D,
                                     w2r + d*SPEC_D, w2i + d*SPEC_D);
        inv_x_kernel<<<NBT*NC, 256>>>();
        dim3 g5(128, NBT);
        fused_tail_kernel<<<g5, 256, FUSED_SMEM>>>(
            gctx + (size_t)d*NBT*64*4096,
            ll_w + (size_t)d*4096, ll_b + d*64, ln_g + d*64, ln_b + d*64);
    }
    head_kernel<<<256, 256>>>(Wt_w, Wt_b, Q_w, Q_b, out);
}

// round 5
// speedup vs baseline: 1.1353x; 1.0089x over previous
#include <cuda_runtime.h>
#include <math.h>

#ifndef M_PI
#define M_PI 3.14159265358979323846
#endif

// Problem constants
#define NBT 48      // B*T_IN = 4*12
#define NC  64      // WIDTH
#define NX  128
#define NY  128
#define NB  4
#define TIN 12
#define TOUT 4
#define UD  3
#define NDEPTH 4

typedef unsigned long long u64;

// ---------------- packed f32x2 helpers (sm_100+) ---------------------------
__device__ __forceinline__ u64 f2fma(u64 a, u64 b, u64 c) {
    u64 r; asm("fma.rn.f32x2 %0,%1,%2,%3;" : "=l"(r) : "l"(a), "l"(b), "l"(c)); return r;
}
__device__ __forceinline__ u64 f2sub(u64 a, u64 b) {
    u64 r; asm("sub.rn.f32x2 %0,%1,%2;" : "=l"(r) : "l"(a), "l"(b)); return r;
}
__device__ __forceinline__ u64 f2pack(float lo, float hi) {
    u64 r; asm("mov.b64 %0,{%1,%2};" : "=l"(r) : "f"(lo), "f"(hi)); return r;
}
__device__ __forceinline__ u64 f2dup(float v) { return f2pack(v, v); }
__device__ __forceinline__ float2 f2unpack(u64 a) {
    float2 r; asm("mov.b64 {%0,%1},%2;" : "=f"(r.x), "=f"(r.y) : "l"(a)); return r;
}
__device__ __forceinline__ u64 f2neg(u64 a) { return a ^ 0x8000000080000000ULL; }

// ---------------- scratch (device globals; allocation-free) ----------------
__device__ float g_X [NBT*NC*NX*NY];     // activation (bt,c,x,y)
__device__ float g_Yf[NBT*NC*NX*32];     // fwd-y result (row, 16re+16im)
__device__ float g_Zr[NBT*NC*512];       // fwd spectrum real (bt,c,mode)
__device__ float g_Zi[NBT*NC*512];       // fwd spectrum imag
__device__ float g_Or[NBT*NC*512];       // mixed spectrum real
__device__ float g_Oi[NBT*NC*512];       // mixed spectrum imag
__device__ float g_Xi[NBT*NC*NX*32];     // inv-x result (bt,o,x,16re+16im)
// DFT basis tables
__device__ float g_Wfy2[64*32*2];        // [ypair][k] packed pair {w(2y,k), w(2y+1,k)}
__device__ float g_Wfx[128*32*2];        // [x][m] (re,im) fwd e^{-i}
__device__ float g_Wix[32*128*2];        // [m][x] (re,im) inv e^{+i}/128
__device__ float g_Cy [16*128];          // inverse-y c2r cos basis
__device__ float g_Sy [16*128];          // inverse-y c2r sin basis

// ---------------- table init (exact angle reduction, double trig) ----------
__global__ void init_tables_kernel() {
    int tid = blockIdx.x * blockDim.x + threadIdx.x;
    if (tid < 64*32) {
        int yp = tid >> 5, k = tid & 31;
        int kk = k & 15;
        for (int j = 0; j < 2; j++) {
            int y = 2*yp + j;
            double th = (2.0 * M_PI / 128.0) * (double)((kk * y) & 127);
            g_Wfy2[tid*2 + j] = (k < 16) ? (float)cos(th) : (float)(-sin(th));
        }
    }
    if (tid < 128*32) {
        int x = tid >> 5, m = tid & 31;
        int kx = (m < 16) ? m : (96 + m);
        double th = (2.0 * M_PI / 128.0) * (double)((kx * x) & 127);
        g_Wfx[2*tid]   = (float)cos(th);
        g_Wfx[2*tid+1] = (float)(-sin(th));
    }
    if (tid < 32*128) {
        int m = tid >> 7, x = tid & 127;
        int kx = (m < 16) ? m : (96 + m);
        double th = (2.0 * M_PI / 128.0) * (double)((kx * x) & 127);
        g_Wix[2*tid]   = (float)(cos(th) / 128.0);
        g_Wix[2*tid+1] = (float)(sin(th) / 128.0);
    }
    if (tid < 16*128) {
        int k = tid >> 7, y = tid & 127;
        if (k == 0) { g_Cy[tid] = 1.0f/128.0f; g_Sy[tid] = 0.0f; }
        else {
            double th = (2.0 * M_PI / 128.0) * (double)((k * y) & 127);
            g_Cy[tid] = (float)( 2.0 * cos(th) / 128.0);
            g_Sy[tid] = (float)(-2.0 * sin(th) / 128.0);
        }
    }
}

// ---------------- lifting: 3 -> 64 channels --------------------------------
__global__ __launch_bounds__(256) void lift_kernel(
    const float* __restrict__ in, const float* __restrict__ Pw,
    const float* __restrict__ Pb)
{
    __shared__ float sPw[64*3];
    __shared__ float sPb[64];
    int tid = threadIdx.x;
    if (tid < 192) sPw[tid] = Pw[tid];
    if (tid < 64)  sPb[tid] = Pb[tid];
    __syncthreads();
    int idx = blockIdx.x * 256 + tid;            // over 48*16384
    int bt = idx >> 14, xy = idx & 16383;
    float a0 = in[(bt*3 + 0)*16384 + xy];
    float a1 = in[(bt*3 + 1)*16384 + xy];
    float a2 = in[(bt*3 + 2)*16384 + xy];
    float* dst = g_X + (size_t)bt * NC * 16384 + xy;
#pragma unroll
    for (int o = 0; o < 64; o++)
        dst[(size_t)o * 16384] = sPb[o] + sPw[o*3]*a0 + sPw[o*3+1]*a1 + sPw[o*3+2]*a2;
}

// ---------------- forward DFT over y (8 rows/warp, quad loads) -------------
// block = 64 rows (8 warps x 8 rows); grid = 393216/64 = 6144
__global__ __launch_bounds__(256) void fwd_y_kernel() {
    __shared__ float sW2[4096];   // 16KB packed-pair table (u64 view)
    __shared__ float sR[8192];    // 64 rows x 128  (32KB)
    int tid = threadIdx.x;
    for (int i = tid; i < 4096; i += 256) sW2[i] = g_Wfy2[i];
    size_t rowBase = (size_t)blockIdx.x * 64;
    const float* src = g_X + rowBase * 128;
    for (int i = tid; i < 8192; i += 256) sR[i] = src[i];
    __syncthreads();
    int warp = tid >> 5, lane = tid & 31;
    const float* r0 = sR + warp * 8 * 128;
    const u64* w2 = (const u64*)sW2;
    u64 acc[8];
#pragma unroll
    for (int r = 0; r < 8; r++) acc[r] = 0ULL;
#pragma unroll 4
    for (int yq = 0; yq < 32; yq++) {
        u64 wA = w2[(2*yq)*32 + lane];
        u64 wB = w2[(2*yq+1)*32 + lane];
#pragma unroll
        for (int r = 0; r < 8; r++) {
            ulonglong2 q = *(const ulonglong2*)(r0 + r*128 + 4*yq);
            acc[r] = f2fma(q.x, wA, acc[r]);
            acc[r] = f2fma(q.y, wB, acc[r]);
        }
    }
#pragma unroll
    for (int r = 0; r < 8; r++) {
        float2 p = f2unpack(acc[r]);
        g_Yf[(rowBase + warp*8 + r)*32 + lane] = p.x + p.y;
    }
}

// ---------------- forward DFT over x (2 fields/block, smem twiddles) -------
// grid = 1536; block = 128; dynamic smem 65536 B
// layout (floats): sY0 [0,4096) | sY1 [4096,8192) | sW (float2) [8192..]
__global__ __launch_bounds__(128) void fwd_x_kernel() {
    extern __shared__ float smx[];
    float*  sY0 = smx;
    float*  sY1 = smx + 4096;
    float2* sW  = (float2*)(smx + 8192);
    int tid = threadIdx.x;
    const float* src = g_Yf + (size_t)blockIdx.x * 8192;
    for (int i = tid; i < 4096; i += 128) { sY0[i] = src[i]; sY1[i] = src[4096 + i]; }
    const float2* wsrc = (const float2*)g_Wfx;
    for (int i = tid; i < 4096; i += 128) sW[i] = wsrc[i];
    __syncthreads();
    int m   = tid >> 2;                 // 0..31
    int ky0 = (tid & 3) * 4;            // 0,4,8,12 : this thread does ky0..ky0+3
    u64 rA[2][2], rB[2][2], ii[2][2];
#pragma unroll
    for (int f = 0; f < 2; f++)
#pragma unroll
        for (int p = 0; p < 2; p++) { rA[f][p] = 0ULL; rB[f][p] = 0ULL; ii[f][p] = 0ULL; }
#pragma unroll 2
    for (int x = 0; x < 128; x++) {
        float2 w = sW[x*32 + m];
        u64 wr2 = f2dup(w.x), wi2 = f2dup(w.y);
        u64 a00 = *(const u64*)(sY0 + x*32 + ky0);
        u64 b00 = *(const u64*)(sY0 + x*32 + 16 + ky0);
        u64 a01 = *(const u64*)(sY0 + x*32 + ky0 + 2);
        u64 b01 = *(const u64*)(sY0 + x*32 + 18 + ky0);
        u64 a10 = *(const u64*)(sY1 + x*32 + ky0);
        u64 b10 = *(const u64*)(sY1 + x*32 + 16 + ky0);
        u64 a11 = *(const u64*)(sY1 + x*32 + ky0 + 2);
        u64 b11 = *(const u64*)(sY1 + x*32 + 18 + ky0);
        rA[0][0] = f2fma(a00, wr2, rA[0][0]);  rB[0][0] = f2fma(b00, wi2, rB[0][0]);
        ii[0][0] = f2fma(a00, wi2, ii[0][0]);  ii[0][0] = f2fma(b00, wr2, ii[0][0]);
        rA[0][1] = f2fma(a01, wr2, rA[0][1]);  rB[0][1] = f2fma(b01, wi2, rB[0][1]);
        ii[0][1] = f2fma(a01, wi2, ii[0][1]);  ii[0][1] = f2fma(b01, wr2, ii[0][1]);
        rA[1][0] = f2fma(a10, wr2, rA[1][0]);  rB[1][0] = f2fma(b10, wi2, rB[1][0]);
        ii[1][0] = f2fma(a10, wi2, ii[1][0]);  ii[1][0] = f2fma(b10, wr2, ii[1][0]);
        rA[1][1] = f2fma(a11, wr2, rA[1][1]);  rB[1][1] = f2fma(b11, wi2, rB[1][1]);
        ii[1][1] = f2fma(a11, wi2, ii[1][1]);  ii[1][1] = f2fma(b11, wr2, ii[1][1]);
    }
#pragma unroll
    for (int f = 0; f < 2; f++) {
        size_t base = ((size_t)(blockIdx.x*2 + f))*512 + m*16 + ky0;
        *(u64*)(g_Zr + base)     = f2sub(rA[f][0], rB[f][0]);
        *(u64*)(g_Zr + base + 2) = f2sub(rA[f][1], rB[f][1]);
        *(u64*)(g_Zi + base)     = ii[f][0];
        *(u64*)(g_Zi + base + 2) = ii[f][1];
    }
}

// ---------------- per-mode 64x64 complex channel mix (2 modes/thread) ------
__global__ __launch_bounds__(128) void mode_mix_kernel(
    const float* __restrict__ w1r, const float* __restrict__ w1i,
    const float* __restrict__ w2r, const float* __restrict__ w2i)
{
    int mp    = blockIdx.x * 128 + threadIdx.x;   // mode-pair 0..255
    int mode0 = mp * 2;
    int half  = mode0 >> 8;
    int ml    = mode0 & 255;
    const float* Wr = half ? w2r : w1r;
    const float* Wi = half ? w2i : w1i;
    int bt0 = blockIdx.y * 4, o0 = blockIdx.z * 4;
    u64 aR[4][4], aI[4][4];
#pragma unroll
    for (int b = 0; b < 4; b++)
#pragma unroll
        for (int o = 0; o < 4; o++) { aR[b][o] = 0ULL; aI[b][o] = 0ULL; }

    for (int i = 0; i < 64; i++) {
        u64 zr[4], zi[4];
#pragma unroll
        for (int b = 0; b < 4; b++) {
            size_t zb = ((size_t)(bt0 + b)*64 + i)*512 + mode0;
            zr[b] = *(const u64*)(g_Zr + zb);
            zi[b] = *(const u64*)(g_Zi + zb);
        }
#pragma unroll
        for (int o = 0; o < 4; o++) {
            size_t wb = ((size_t)i*64 + (o0 + o))*256 + ml;
            u64 wr2  = *(const u64*)(Wr + wb);
            u64 wi2  = *(const u64*)(Wi + wb);
            u64 wi2n = f2neg(wi2);
#pragma unroll
            for (int b = 0; b < 4; b++) {
                aR[b][o] = f2fma(zr[b], wr2,  aR[b][o]);
                aR[b][o] = f2fma(zi[b], wi2n, aR[b][o]);
                aI[b][o] = f2fma(zr[b], wi2,  aI[b][o]);
                aI[b][o] = f2fma(zi[b], wr2,  aI[b][o]);
            }
        }
    }
#pragma unroll
    for (int b = 0; b < 4; b++)
#pragma unroll
        for (int o = 0; o < 4; o++) {
            size_t ob = ((size_t)(bt0 + b)*64 + (o0 + o))*512 + mode0;
            *(u64*)(g_Or + ob) = aR[b][o];
            *(u64*)(g_Oi + ob) = aI[b][o];
        }
}

// ---------------- inverse DFT over x ---------------------------------------
__global__ __launch_bounds__(256) void inv_x_kernel() {
    __shared__ float sOr[512], sOi[512];
    int tid = threadIdx.x;
    const float* srcr = g_Or + (size_t)blockIdx.x * 512;
    const float* srci = g_Oi + (size_t)blockIdx.x * 512;
    for (int i = tid; i < 512; i += 256) { sOr[i] = srcr[i]; sOi[i] = srci[i]; }
    __syncthreads();
    int x  = tid >> 1;
    int kb = (tid & 1) * 8;
    u64 arA[4], arB[4], ai[4];
#pragma unroll
    for (int j = 0; j < 4; j++) { arA[j] = 0ULL; arB[j] = 0ULL; ai[j] = 0ULL; }
#pragma unroll 4
    for (int m = 0; m < 32; m++) {
        float2 w = *(const float2*)(g_Wix + (m*128 + x)*2);
        u64 wr2 = f2dup(w.x), wi2 = f2dup(w.y);
#pragma unroll
        for (int j = 0; j < 4; j++) {
            u64 pr = *(const u64*)(sOr + m*16 + kb + 2*j);
            u64 pi = *(const u64*)(sOi + m*16 + kb + 2*j);
            arA[j] = f2fma(pr, wr2, arA[j]);
            arB[j] = f2fma(pi, wi2, arB[j]);
            ai[j]  = f2fma(pr, wi2, ai[j]);
            ai[j]  = f2fma(pi, wr2, ai[j]);
        }
    }
    float* dst = g_Xi + ((size_t)blockIdx.x * 128 + x) * 32;
#pragma unroll
    for (int j = 0; j < 4; j++) {
        *(u64*)(dst + kb + 2*j)      = f2sub(arA[j], arB[j]);
        *(u64*)(dst + 16 + kb + 2*j) = ai[j];
    }
}

// ---------------- fused: inv-y + 1x1 mix + LN + GELU + context, in place ---
// one block per (bt, x) line; 256 threads; dyn smem 25536 floats = 102144 B
__global__ __launch_bounds__(256) void fused_tail_kernel(
    const float* __restrict__ gctxd,
    const float* __restrict__ llw,
    const float* __restrict__ llb,
    const float* __restrict__ lng, const float* __restrict__ lnb)
{
    extern __shared__ float sm[];
    float* sXV  = sm;
    u64*   sLLd = (u64*)(sm + 8192);
    u64*   sXid = (u64*)(sm + 16384);
    float* sCy  = sm + 20480;
    float* sSy  = sm + 22528;
    float* sPS  = sm + 24576;
    float* sPQ  = sm + 24832;
    float* sMu  = sm + 25088;
    float* sRs  = sm + 25216;
    float* sLNg = sm + 25344;
    float* sLNb = sm + 25408;
    float* sLLb = sm + 25472;

    int tid = threadIdx.x;
    int x   = blockIdx.x;
    int bt  = blockIdx.y;

    // phase 1: loads (+ build dup'd operand tables)
    for (int i = tid; i < 8192; i += 256) {
        int c = i >> 7, y = i & 127;
        sXV[i] = g_X[(((size_t)bt*64 + c)*128 + x)*128 + y];
    }
    for (int i = tid; i < 4096; i += 256) sLLd[i] = f2dup(llw[i]);
    for (int i = tid; i < 2048; i += 256) {
        int o = i >> 5, k = i & 31;
        sXid[i] = f2dup(g_Xi[(((size_t)bt*64 + o)*128 + x)*32 + k]);
    }
    for (int i = tid; i < 2048; i += 256) { sCy[i] = g_Cy[i]; sSy[i] = g_Sy[i]; }
    if (tid < 64) { sLNg[tid] = lng[tid]; sLNb[tid] = lnb[tid]; sLLb[tid] = llb[tid]; }
    __syncthreads();

    // phase 2: V[o][y] = local-linear + inverse-y
    int o0  = (tid >> 5) * 8;           // 8 o per thread
    int tx4 = (tid & 31) * 4;           // 4 y per thread = 2 pairs
    u64 acc0[8], acc1[8];
#pragma unroll
    for (int oo = 0; oo < 8; oo++) { acc0[oo] = 0ULL; acc1[oo] = 0ULL; }

#pragma unroll 2
    for (int c = 0; c < 64; c++) {
        ulonglong2 xv = *(const ulonglong2*)(sXV + c*128 + tx4);
#pragma unroll
        for (int oo = 0; oo < 8; oo++) {
            u64 w2 = sLLd[(o0 + oo)*64 + c];
            acc0[oo] = f2fma(xv.x, w2, acc0[oo]);
            acc1[oo] = f2fma(xv.y, w2, acc1[oo]);
        }
    }
#pragma unroll
    for (int ky = 0; ky < 16; ky++) {
        ulonglong2 cy = *(const ulonglong2*)(sCy + ky*128 + tx4);
        ulonglong2 sy = *(const ulonglong2*)(sSy + ky*128 + tx4);
#pragma unroll
        for (int oo = 0; oo < 8; oo++) {
            u64 xr2 = sXid[(o0 + oo)*32 + ky];
            u64 xi2 = sXid[(o0 + oo)*32 + 16 + ky];
            acc0[oo] = f2fma(xr2, cy.x, acc0[oo]);
            acc0[oo] = f2fma(xi2, sy.x, acc0[oo]);
            acc1[oo] = f2fma(xr2, cy.y, acc1[oo]);
            acc1[oo] = f2fma(xi2, sy.y, acc1[oo]);
        }
    }
    __syncthreads();   // all reads of sXV done; safe to overwrite with V
#pragma unroll
    for (int oo = 0; oo < 8; oo++) {
        float b = sLLb[o0 + oo];
        float2 v0 = f2unpack(acc0[oo]);
        float2 v1 = f2unpack(acc1[oo]);
        *(float4*)(sXV + (o0 + oo)*128 + tx4) =
            make_float4(v0.x + b, v0.y + b, v1.x + b, v1.y + b);
    }
    __syncthreads();

    // phase 3: layernorm stats per y (all 256 threads)
    {
        int yy = tid & 127, oh = tid >> 7;       // each half sums 32 o
        float s = 0.f, ss = 0.f;
        int ob = oh * 32;
        for (int o = ob; o < ob + 32; o++) {
            float v = sXV[o*128 + yy];
            s += v; ss += v*v;
        }
        sPS[tid] = s; sPQ[tid] = ss;
    }
    __syncthreads();
    if (tid < 128) {
        float s = sPS[tid] + sPS[128 + tid];
        float q = sPQ[tid] + sPQ[128 + tid];
        float mu = s * (1.0f/64.0f);
        float var = q * (1.0f/64.0f) - mu*mu;
        sMu[tid] = mu;
        sRs[tid] = rsqrtf(var + 1e-5f);
    }
    __syncthreads();

    // phase 4: normalize + gelu + bilinear context + write back (in place)
    float cxf = x * 0.5f - 0.25f;
    int ix0 = (int)floorf(cxf);
    float wx1 = cxf - (float)ix0, wx0 = 1.0f - wx1;
    int cx0 = min(63, max(0, ix0));
    int cx1 = min(63, max(0, ix0 + 1));
    int y = tid & 127;
    float cyf = y * 0.5f - 0.25f;
    int iy0 = (int)floorf(cyf);
    float wy1 = cyf - (float)iy0, wy0 = 1.0f - wy1;
    int cy0 = min(63, max(0, iy0));
    int cy1 = min(63, max(0, iy0 + 1));

    for (int j = 0; j < 32; j++) {
        int idx = j * 256 + tid;
        int o = idx >> 7;
        float v = sXV[o*128 + y];
        v = (v - sMu[y]) * sRs[y] * sLNg[o] + sLNb[o];
        v = 0.5f * v * (1.0f + erff(v * 0.70710678118654752440f));
        const float* gc = gctxd + ((size_t)bt*64 + o) * 4096;
        float g = wx0 * (wy0 * __ldg(gc + cx0*64 + cy0) + wy1 * __ldg(gc + cx0*64 + cy1))
                + wx1 * (wy0 * __ldg(gc + cx1*64 + cy0) + wy1 * __ldg(gc + cx1*64 + cy1));
        g_X[(((size_t)bt*64 + o)*128 + x)*128 + y] = v + g;
    }
}

// ---------------- temporal aggregation + projection ------------------------
__global__ __launch_bounds__(256) void head_kernel(
    const float* __restrict__ Wtw, const float* __restrict__ Wtb,
    const float* __restrict__ Qw,  const float* __restrict__ Qb,
    float* __restrict__ out)
{
    __shared__ float sWt[48], sWtb[4], sQ[192], sQb[3], sQS[3];
    int tid = threadIdx.x;
    if (tid < 48)  sWt[tid]  = Wtw[tid];
    if (tid < 4)   sWtb[tid] = Wtb[tid];
    if (tid < 192) sQ[tid]   = Qw[tid];
    if (tid < 3)   sQb[tid]  = Qb[tid];
    __syncthreads();
    if (tid < 3) {
        float s = 0.f;
        for (int c = 0; c < 64; c++) s += sQ[tid*64 + c];
        sQS[tid] = s;
    }
    __syncthreads();
    int idx = blockIdx.x * 256 + tid;           // over 4*16384
    int b = idx >> 14, xy = idx & 16383;
    float acc[TOUT][UD] = {};
    for (int c = 0; c < 64; c++) {
        float xv[TIN];
#pragma unroll
        for (int t = 0; t < TIN; t++)
            xv[t] = g_X[(((size_t)(b*TIN + t))*64 + c)*16384 + xy];
        float tt[TOUT];
#pragma unroll
        for (int o = 0; o < TOUT; o++) {
            float s = 0.f;
#pragma unroll
            for (int t = 0; t < TIN; t++) s += sWt[o*TIN + t] * xv[t];
            tt[o] = s;
        }
#pragma unroll
        for (int u = 0; u < UD; u++) {
            float q = sQ[u*64 + c];
#pragma unroll
            for (int o = 0; o < TOUT; o++) acc[o][u] += q * tt[o];
        }
    }
#pragma unroll
    for (int o = 0; o < TOUT; o++)
#pragma unroll
        for (int u = 0; u < UD; u++)
            out[(((size_t)b*TOUT + o)*UD + u)*16384 + xy] =
                acc[o][u] + sWtb[o]*sQS[u] + sQb[u];
}

// ---------------- launcher --------------------------------------------------
extern "C" void kernel_launch(void* const* d_in, const int* in_sizes, int n_in,
                              void* d_out, int out_size)
{
    const float* input = (const float*)d_in[0];
    const float* gctx  = (const float*)d_in[1];
    const float* P_w   = (const float*)d_in[2];
    const float* P_b   = (const float*)d_in[3];
    const float* Q_w   = (const float*)d_in[4];
    const float* Q_b   = (const float*)d_in[5];
    const float* Wt_w  = (const float*)d_in[6];
    const float* Wt_b  = (const float*)d_in[7];
    const float* w1r   = (const float*)d_in[8];
    const float* w1i   = (const float*)d_in[9];
    const float* w2r   = (const float*)d_in[10];
    const float* w2i   = (const float*)d_in[11];
    const float* ll_w  = (const float*)d_in[12];
    const float* ll_b  = (const float*)d_in[13];
    const float* ln_g  = (const float*)d_in[14];
    const float* ln_b  = (const float*)d_in[15];
    float* out = (float*)d_out;

    const int FUSED_SMEM = 25536 * 4;  // 102144 bytes
    const int FWDX_SMEM  = 16384 * 4;  // 65536 bytes
    cudaFuncSetAttribute(fused_tail_kernel,
                         cudaFuncAttributeMaxDynamicSharedMemorySize, FUSED_SMEM);
    cudaFuncSetAttribute(fwd_x_kernel,
                         cudaFuncAttributeMaxDynamicSharedMemorySize, FWDX_SMEM);

    init_tables_kernel<<<16, 256>>>();
    lift_kernel<<<3072, 256>>>(input, P_w, P_b);

    const size_t SPEC_D = (size_t)64*64*16*16;   // per-depth spectral weight block
    for (int d = 0; d < NDEPTH; d++) {
        fwd_y_kernel<<<6144, 256>>>();
        fwd_x_kernel<<<1536, 128, FWDX_SMEM>>>();
        dim3 g3(2, 12, 16);
        mode_mix_kernel<<<g3, 128>>>(w1r + d*SPEC_D, w1i + d*SPEC_D,
                                     w2r + d*SPEC_D, w2i + d*SPEC_D);
        inv_x_kernel<<<NBT*NC, 256>>>();
        dim3 g5(128, NBT);
        fused_tail_kernel<<<g5, 256, FUSED_SMEM>>>(
            gctx + (size_t)d*NBT*64*4096,
            ll_w + (size_t)d*4096, ll_b + d*64, ln_g + d*64, ln_b + d*64);
    }
    head_kernel<<<256, 256>>>(Wt_w, Wt_b, Q_w, Q_b, out);
}